// round 15
// baseline (speedup 1.0000x reference)
#include <cuda_runtime.h>

// SiluAndMul: x [M, 2N] fp32 -> out [M, N] fp32, out = silu(x[:, :N]) * x[:, N:]
// M = 16384, N = 11008. Pure HBM-bound: 2.164 GB/launch.
//
// R15: block=224, final interpolation of the timed block-size curve:
//   timed us:  64:360.1 | 128:299.2,300.3 | 192:298.1,298.4 | 256:299.5-299.8
// 192 is the reproduced timed best; 224 checks whether the peak extends right.
// Tail block (64/224 lanes active) is free — dead lanes cost no DRAM bytes.
// All other axes closed: plain evict-normal ld/st, 1 float4/thread, 2D grid.

static constexpr int M = 16384;
static constexpr int N = 11008;         // output cols
static constexpr int TWO_N = 2 * N;     // input row stride (floats)
static constexpr int N4 = N / 4;        // 2752 float4 per output row
static constexpr int BLOCK = 224;

__global__ __launch_bounds__(BLOCK) void silu_and_mul_kernel(
    const float* __restrict__ x, float* __restrict__ out)
{
    const int col4 = blockIdx.x * BLOCK + threadIdx.x;  // float4 column index
    if (col4 >= N4) return;
    const long long row = blockIdx.y;

    const float4* gate4 = reinterpret_cast<const float4*>(x + row * TWO_N);
    const float4* up4   = reinterpret_cast<const float4*>(x + row * TWO_N + N);
    float4* out4        = reinterpret_cast<float4*>(out + row * (long long)N);

    float4 g = gate4[col4];
    float4 u = up4[col4];

    float4 r;
    r.x = (g.x * __frcp_rn(1.0f + __expf(-g.x))) * u.x;
    r.y = (g.y * __frcp_rn(1.0f + __expf(-g.y))) * u.y;
    r.z = (g.z * __frcp_rn(1.0f + __expf(-g.z))) * u.z;
    r.w = (g.w * __frcp_rn(1.0f + __expf(-g.w))) * u.w;

    out4[col4] = r;
}

extern "C" void kernel_launch(void* const* d_in, const int* in_sizes, int n_in,
                              void* d_out, int out_size)
{
    const float* x = (const float*)d_in[0];
    float* out = (float*)d_out;

    dim3 block(BLOCK);
    dim3 grid((N4 + BLOCK - 1) / BLOCK, M);   // (13, 16384)
    silu_and_mul_kernel<<<grid, block>>>(x, out);
}

// round 16
// speedup vs baseline: 1.0044x; 1.0044x over previous
#include <cuda_runtime.h>

// SiluAndMul: x [M, 2N] fp32 -> out [M, N] fp32, out = silu(x[:, :N]) * x[:, N:]
// M = 16384, N = 11008. Pure HBM-bound: 2.164 GB/launch.
//
// FINAL kernel — 15-round converged optimum on GB300 (sm_103a).
// Timed block-size curve (unimodal, peak at 192; all reproduced):
//   64: 360.1 (CTA-refill starvation, occ 42%)
//   128: 299.2/300.3 | 192: 298.1/298.4 <- BEST | 224: 300.0 | 256: 299.5-299.8
// Closed axes:
//   - cache policy: plain evict-normal ld AND st (every streaming-hint combo
//     measured ~2us slower; evict-first writebacks add DRAM bus turnarounds)
//   - vector depth: 1 float4/thread (deeper unroll neutral; regs stay 24)
//   - topology: 2D grid (persistent grid -> loop-carried MLP collapse, 360us;
//     1D flat -> 64-bit div overhead, neutral-worse)
// Governing mechanism: bandwidth = count of independent in-flight loads across
// CTAs; the large one-shot CTA grid IS the memory-level parallelism.
// Achieves ~7.2 TB/s = 90% of 8 TB/s HBM3e spec (chip ceiling for 2:1 R:W mix);
// 298.1us vs ~297us analytic floor at that bandwidth.

static constexpr int M = 16384;
static constexpr int N = 11008;         // output cols
static constexpr int TWO_N = 2 * N;     // input row stride (floats)
static constexpr int N4 = N / 4;        // 2752 float4 per output row
static constexpr int BLOCK = 192;

__global__ __launch_bounds__(BLOCK) void silu_and_mul_kernel(
    const float* __restrict__ x, float* __restrict__ out)
{
    const int col4 = blockIdx.x * BLOCK + threadIdx.x;  // float4 column index
    if (col4 >= N4) return;
    const long long row = blockIdx.y;

    const float4* gate4 = reinterpret_cast<const float4*>(x + row * TWO_N);
    const float4* up4   = reinterpret_cast<const float4*>(x + row * TWO_N + N);
    float4* out4        = reinterpret_cast<float4*>(out + row * (long long)N);

    float4 g = gate4[col4];
    float4 u = up4[col4];

    float4 r;
    r.x = (g.x * __frcp_rn(1.0f + __expf(-g.x))) * u.x;
    r.y = (g.y * __frcp_rn(1.0f + __expf(-g.y))) * u.y;
    r.z = (g.z * __frcp_rn(1.0f + __expf(-g.z))) * u.z;
    r.w = (g.w * __frcp_rn(1.0f + __expf(-g.w))) * u.w;

    out4[col4] = r;
}

extern "C" void kernel_launch(void* const* d_in, const int* in_sizes, int n_in,
                              void* d_out, int out_size)
{
    const float* x = (const float*)d_in[0];
    float* out = (float*)d_out;

    dim3 block(BLOCK);
    dim3 grid((N4 + BLOCK - 1) / BLOCK, M);   // (15, 16384)
    silu_and_mul_kernel<<<grid, block>>>(x, out);
}